// round 17
// baseline (speedup 1.0000x reference)
#include <cuda_runtime.h>

// D fixed by the problem (256 floats per row).
#define D     256
#define D4    64              // float4s per row
#define TPB   128
#define WPB   (TPB / 32)
#define NBLK  1216            // 152 SMs x 8 resident blocks: one persistent wave

// Per-block partial sums (every slot written every call -> no zeroing needed).
__device__ double   d_part[NBLK];
// Completion counter: 0 at start, last block resets it -> replay-deterministic.
__device__ unsigned d_count;

__device__ __forceinline__ float dot4(float4 a, float4 b) {
    return a.x * b.x + a.y * b.y + a.z * b.z + a.w * b.w;
}

// ---------------------------------------------------------------------------
// Champion loop (R8 structure, bit-identical math) + g-rows parked in
// per-lane SMEM slots instead of registers:
//   each lane writes gsm[wid][t][lane] / [lane+32] and later reads ONLY its
//   own slots -> no syncs, no bank conflicts. This frees ~16 registers so
//   the kernel fits the (128, 8) budget: 32 warps/SM with zero spills.
//   total = sum_i  dot(h1_i, g2_b)*ginv(h1_i)*ginv(g2_b)
//               +  dot(h2_i, g1_b)*ginv(h2_i)*ginv(g1_b),   b = batch[i]
// batch is sorted: g rows are refreshed only on (rare) warp-uniform b change;
// inverse norms computed inline at that point. 8 LDG.128 front-batched/pair.
// ---------------------------------------------------------------------------
__global__ void __launch_bounds__(TPB, 8)
main_k(const float* __restrict__ h1, const float* __restrict__ h2,
       const float* __restrict__ g1, const float* __restrict__ g2,
       const int*   __restrict__ batch, float* __restrict__ out,
       int N, int G)
{
    const int lane  = threadIdx.x & 31;
    const int wid   = threadIdx.x >> 5;
    const int gwarp = blockIdx.x * WPB + wid;
    const int nw    = gridDim.x * WPB;

    const int per = (N + nw - 1) / nw;
    const int i0  = gwarp * per;
    const int i1  = min(N, i0 + per);

    // Per-warp g cache: [warp][tensor 0=g1,1=g2][chunk]: 4*2*64*16B = 8 KB.
    __shared__ float4 gsm[WPB][2][D4];

    double acc = 0.0;

    int   bcur = -1;
    float gi1 = 0.f, gi2 = 0.f;               // lane-uniform inverse norms

#define RELOAD_G(B)                                                          \
    do {                                                                     \
        bcur = (B);                                                          \
        const float4* pg1 = reinterpret_cast<const float4*>(g1) + (size_t)bcur * D4; \
        const float4* pg2 = reinterpret_cast<const float4*>(g2) + (size_t)bcur * D4; \
        float4 u0 = pg1[lane], u1 = pg1[lane + 32];                          \
        float4 w0 = pg2[lane], w1 = pg2[lane + 32];                          \
        gsm[wid][0][lane] = u0; gsm[wid][0][lane + 32] = u1;                 \
        gsm[wid][1][lane] = w0; gsm[wid][1][lane + 32] = w1;                 \
        float sg1 = dot4(u0, u0) + dot4(u1, u1);                             \
        float sg2 = dot4(w0, w0) + dot4(w1, w1);                             \
        _Pragma("unroll")                                                    \
        for (int off = 16; off > 0; off >>= 1) {                             \
            sg1 += __shfl_xor_sync(0xffffffffu, sg1, off);                   \
            sg2 += __shfl_xor_sync(0xffffffffu, sg2, off);                   \
        }                                                                    \
        gi1 = rsqrtf(fmaxf(sg1, 1e-24f));                                    \
        gi2 = rsqrtf(fmaxf(sg2, 1e-24f));                                    \
    } while (0)

    int i = i0;
    for (; i + 2 <= i1; i += 2) {
        const int ba = batch[i];
        const int bb = batch[i + 1];          // sorted: ba <= bb

        // Batch all 8 h loads up front (MLP=8, evict-first streaming).
        const float4* pa1 = reinterpret_cast<const float4*>(h1) + (size_t)i * D4;
        const float4* pa2 = reinterpret_cast<const float4*>(h2) + (size_t)i * D4;
        const float4* pb1 = reinterpret_cast<const float4*>(h1) + (size_t)(i + 1) * D4;
        const float4* pb2 = reinterpret_cast<const float4*>(h2) + (size_t)(i + 1) * D4;
        float4 a0 = __ldcs(pa1 + lane), a1 = __ldcs(pa1 + lane + 32);
        float4 e0 = __ldcs(pa2 + lane), e1 = __ldcs(pa2 + lane + 32);
        float4 b0 = __ldcs(pb1 + lane), b1 = __ldcs(pb1 + lane + 32);
        float4 f0 = __ldcs(pb2 + lane), f1 = __ldcs(pb2 + lane + 32);

        if (ba != bcur) RELOAD_G(ba);         // warp-uniform, rare (~1/30)
        const float gia1 = gi1, gia2 = gi2;   // snapshot for row a

        // Dots: g chunks come back from this lane's own smem slots.
        float da1 = dot4(a0, gsm[wid][1][lane]) + dot4(a1, gsm[wid][1][lane + 32]);
        float sa1 = dot4(a0, a0) + dot4(a1, a1);
        float da2 = dot4(e0, gsm[wid][0][lane]) + dot4(e1, gsm[wid][0][lane + 32]);
        float sa2 = dot4(e0, e0) + dot4(e1, e1);

        if (bb != bcur) RELOAD_G(bb);         // row a's dots already formed

        float db1 = dot4(b0, gsm[wid][1][lane]) + dot4(b1, gsm[wid][1][lane + 32]);
        float sb1 = dot4(b0, b0) + dot4(b1, b1);
        float db2 = dot4(f0, gsm[wid][0][lane]) + dot4(f1, gsm[wid][0][lane + 32]);
        float sb2 = dot4(f0, f0) + dot4(f1, f1);

        // 8 interleaved butterfly chains (identical tree to champion).
#pragma unroll
        for (int off = 16; off > 0; off >>= 1) {
            da1 += __shfl_xor_sync(0xffffffffu, da1, off);
            sa1 += __shfl_xor_sync(0xffffffffu, sa1, off);
            da2 += __shfl_xor_sync(0xffffffffu, da2, off);
            sa2 += __shfl_xor_sync(0xffffffffu, sa2, off);
            db1 += __shfl_xor_sync(0xffffffffu, db1, off);
            sb1 += __shfl_xor_sync(0xffffffffu, sb1, off);
            db2 += __shfl_xor_sync(0xffffffffu, db2, off);
            sb2 += __shfl_xor_sync(0xffffffffu, sb2, off);
        }

        const float va = da1 * rsqrtf(fmaxf(sa1, 1e-24f)) * gia2
                       + da2 * rsqrtf(fmaxf(sa2, 1e-24f)) * gia1;
        const float vb = db1 * rsqrtf(fmaxf(sb1, 1e-24f)) * gi2
                       + db2 * rsqrtf(fmaxf(sb2, 1e-24f)) * gi1;
        acc += (double)va;
        acc += (double)vb;
    }

    if (i < i1) {                              // odd remainder row
        const int b = batch[i];
        const float4* ph1 = reinterpret_cast<const float4*>(h1) + (size_t)i * D4;
        const float4* ph2 = reinterpret_cast<const float4*>(h2) + (size_t)i * D4;
        float4 x0 = __ldcs(ph1 + lane), x1 = __ldcs(ph1 + lane + 32);
        float4 y0 = __ldcs(ph2 + lane), y1 = __ldcs(ph2 + lane + 32);

        if (b != bcur) RELOAD_G(b);

        float d1 = dot4(x0, gsm[wid][1][lane]) + dot4(x1, gsm[wid][1][lane + 32]);
        float s1 = dot4(x0, x0) + dot4(x1, x1);
        float d2 = dot4(y0, gsm[wid][0][lane]) + dot4(y1, gsm[wid][0][lane + 32]);
        float s2 = dot4(y0, y0) + dot4(y1, y1);
#pragma unroll
        for (int off = 16; off > 0; off >>= 1) {
            d1 += __shfl_xor_sync(0xffffffffu, d1, off);
            s1 += __shfl_xor_sync(0xffffffffu, s1, off);
            d2 += __shfl_xor_sync(0xffffffffu, d2, off);
            s2 += __shfl_xor_sync(0xffffffffu, s2, off);
        }
        const float v = d1 * rsqrtf(fmaxf(s1, 1e-24f)) * gi2
                      + d2 * rsqrtf(fmaxf(s2, 1e-24f)) * gi1;
        acc += (double)v;
    }
#undef RELOAD_G

    // ---- block-level partial ----
    __shared__ double sred[WPB];
    __shared__ bool   is_last;
    if (lane == 0) sred[wid] = acc;
    __syncthreads();
    if (threadIdx.x == 0) {
        double t = 0.0;
#pragma unroll
        for (int w = 0; w < WPB; ++w) t += sred[w];
        d_part[blockIdx.x] = t;
        __threadfence();
        unsigned prev = atomicAdd(&d_count, 1u);
        is_last = (prev == (unsigned)(NBLK - 1));
    }
    __syncthreads();

    // ---- last block: fixed-order deterministic final reduction ----
    if (is_last) {
        __shared__ double s[TPB];
        double t = 0.0;
        for (int k = threadIdx.x; k < NBLK; k += TPB)
            t += __ldcg(&d_part[k]);
        s[threadIdx.x] = t;
        __syncthreads();
#pragma unroll
        for (int off = TPB / 2; off > 0; off >>= 1) {
            if (threadIdx.x < off) s[threadIdx.x] += s[threadIdx.x + off];
            __syncthreads();
        }
        if (threadIdx.x == 0) {
            *out = (float)(s[0] / (double)G);
            d_count = 0;                       // reset for next graph replay
        }
    }
}

extern "C" void kernel_launch(void* const* d_in, const int* in_sizes, int n_in,
                              void* d_out, int out_size)
{
    const float* h1    = (const float*)d_in[0];
    const float* h2    = (const float*)d_in[1];
    const float* g1    = (const float*)d_in[2];
    const float* g2    = (const float*)d_in[3];
    const int*   batch = (const int*)d_in[4];   // jax default int32 (x64 disabled)

    const int N = in_sizes[4];          // rows in h1/h2
    const int G = in_sizes[2] / D;      // rows in g1/g2

    main_k<<<NBLK, TPB>>>(h1, h2, g1, g2, batch, (float*)d_out, N, G);
}